// round 9
// baseline (speedup 1.0000x reference)
#include <cuda_runtime.h>
#include <cstdint>
#include <math_constants.h>

// Problem constants
#define B_DIM 64
#define S_DIM 2048
#define D_DIM 1024

// 296 CTAs x 8 warps = 2368 warps = 64 batches x 37 "slots".
// 296 = 148 SMs x occ 2 -> exactly one fully-resident wave (spin-safe).
#define WARPS_PER_CTA 8
#define THREADS (WARPS_PER_CTA * 32)
#define GRID1 296
#define NSPLITS 37
#define VEC 8                       // 8 float4 = 32 floats per lane
#define NSTAGES 3                   // cp.async ring depth per warp
#define CHUNK 4                     // rows per work-steal grab
#define NCHUNKS (S_DIM / CHUNK)     // 512 per batch
#define COMBINE_CTA0 (GRID1 - B_DIM)

#define RING_F4_PER_WARP (NSTAGES * (D_DIM / 4))
#define DYN_SMEM_BYTES (WARPS_PER_CTA * RING_F4_PER_WARP * 16)   // 96 KB

// Scratch (device globals: allocation-free)  ~9.7 MB
__device__ float g_acc[(size_t)B_DIM * NSPLITS * D_DIM];
__device__ float g_m[B_DIM * NSPLITS];
__device__ float g_l[B_DIM * NSPLITS];
__device__ int   g_cnt[B_DIM];      // arrivals;  reset by combiner each run
__device__ int   g_cursor[B_DIM];   // work-steal cursors; reset by combiner

extern __shared__ float4 s_ring[];  // [WARPS_PER_CTA][NSTAGES][D_DIM/4]

__device__ __forceinline__ void waitg(int n) {
    if (n <= 0)      asm volatile("cp.async.wait_group 0;" ::: "memory");
    else if (n == 1) asm volatile("cp.async.wait_group 1;" ::: "memory");
    else             asm volatile("cp.async.wait_group 2;" ::: "memory");
}

// ---------------------------------------------------------------------------
// Fused kernel with dynamic within-batch work stealing.
// Phase 1: the 37 warps of a batch drain a shared atomic chunk cursor
//          (4 rows/grab); unmasked rows stream through a 3-deep cp.async
//          ring so row k's compute overlaps rows k+1,k+2's loads.
// Phase 2: release partials via threadfence+counter; 64 designated CTAs
//          spin and merge (single fully-resident wave -> no deadlock).
// ---------------------------------------------------------------------------
__global__ __launch_bounds__(THREADS, 2)
void luong_fused_kernel(const int*   __restrict__ enc_mask,
                        const float* __restrict__ enc_out,
                        const float* __restrict__ dec_hid,
                        float*       __restrict__ out)
{
    const int tid  = threadIdx.x;
    const int warp = tid >> 5;
    const int lane = tid & 31;
    const int gw   = blockIdx.x * WARPS_PER_CTA + warp;   // 0..2367
    const int b    = gw / NSPLITS;                        // batch
    const int s    = gw - b * NSPLITS;                    // partial slot

    float4* ring = s_ring + (size_t)warp * RING_F4_PER_WARP;

    // dec_hid slice in registers (8 float4 per lane)
    float4 h[VEC];
    {
        const float4* hp = reinterpret_cast<const float4*>(dec_hid + (size_t)b * D_DIM);
        #pragma unroll
        for (int i = 0; i < VEC; i++) h[i] = hp[i * 32 + lane];
    }

    const int*   mrow = enc_mask + (size_t)b * S_DIM;
    const float* base = enc_out + (size_t)b * S_DIM * D_DIM;

    // --- dynamic row provider: per-batch atomic chunk cursor ---
    uint32_t cbits = 0;     // bitmap of remaining unmasked rows in chunk
    int      cbase = 0;
    bool     done  = false;

    auto next_row = [&]() -> int {          // next unmasked row or -1
        while (cbits == 0u) {
            if (done) return -1;
            int c = 0;
            if (lane == 0) c = atomicAdd(&g_cursor[b], 1);
            c = __shfl_sync(0xFFFFFFFFu, c, 0);
            if (c >= NCHUNKS) { done = true; return -1; }
            cbase = c * CHUNK;
            const int mv = (lane < CHUNK) ? __ldg(mrow + cbase + lane) : 1;
            cbits = __ballot_sync(0xFFFFFFFFu, mv == 0);
        }
        const int r = cbase + __ffs(cbits) - 1;
        cbits &= cbits - 1u;
        return r;
    };

    auto issue = [&](int st, int r) {       // async-load row r into stage st
        const float4* src = reinterpret_cast<const float4*>(base + (size_t)r * D_DIM);
        uint32_t dst0 = (uint32_t)__cvta_generic_to_shared(ring + st * (D_DIM / 4));
        #pragma unroll
        for (int i = 0; i < VEC; i++) {
            asm volatile("cp.async.cg.shared.global [%0], [%1], 16;"
                         :: "r"(dst0 + (uint32_t)((i * 32 + lane) * 16)),
                            "l"(src + i * 32 + lane) : "memory");
        }
        asm volatile("cp.async.commit_group;" ::: "memory");
    };

    float m = -CUDART_INF_F;
    float l = 0.0f;
    float acc[VEC * 4];
    #pragma unroll
    for (int j = 0; j < VEC * 4; j++) acc[j] = 0.0f;

    // Prologue: fill ring
    int r = next_row();
    int pend = 0, head = 0, tail = 0;
    while (r >= 0 && pend < NSTAGES) {
        issue(tail, r);
        tail = (tail + 1 == NSTAGES) ? 0 : tail + 1;
        pend++;
        r = next_row();
    }

    // Mainloop: consume oldest stage, refill it, advance
    while (pend > 0) {
        waitg(pend - 1);                    // oldest group complete
        pend--;

        const float4* xs = ring + head * (D_DIM / 4);

        float d0 = 0.f, d1 = 0.f, d2 = 0.f, d3 = 0.f;
        #pragma unroll
        for (int i = 0; i < VEC; i++) {
            const float4 v = xs[i * 32 + lane];
            d0 = fmaf(v.x, h[i].x, d0);
            d1 = fmaf(v.y, h[i].y, d1);
            d2 = fmaf(v.z, h[i].z, d2);
            d3 = fmaf(v.w, h[i].w, d3);
        }
        float dsum = (d0 + d1) + (d2 + d3);
        #pragma unroll
        for (int o = 16; o > 0; o >>= 1)
            dsum += __shfl_xor_sync(0xFFFFFFFFu, dsum, o);

        if (dsum > m) {                     // warp-uniform; ~log(n) times
            const float scale = __expf(m - dsum);   // exp(-inf)=0 first row
            l *= scale;
            #pragma unroll
            for (int j = 0; j < VEC * 4; j++) acc[j] *= scale;
            m = dsum;
        }
        const float p = __expf(dsum - m);
        l += p;
        #pragma unroll
        for (int i = 0; i < VEC; i++) {
            const float4 v = xs[i * 32 + lane];   // smem re-read (cheap)
            acc[i * 4 + 0] = fmaf(p, v.x, acc[i * 4 + 0]);
            acc[i * 4 + 1] = fmaf(p, v.y, acc[i * 4 + 1]);
            acc[i * 4 + 2] = fmaf(p, v.z, acc[i * 4 + 2]);
            acc[i * 4 + 3] = fmaf(p, v.w, acc[i * 4 + 3]);
        }

        if (r >= 0) {                       // refill freed stage
            issue(head, r);
            pend++;
            r = next_row();
        }
        head = (head + 1 == NSTAGES) ? 0 : head + 1;
    }

    // Publish partials, then release-arrive.
    const int sidx = b * NSPLITS + s;
    float4* ap = reinterpret_cast<float4*>(g_acc + (size_t)sidx * D_DIM);
    #pragma unroll
    for (int i = 0; i < VEC; i++) {
        float4 v;
        v.x = acc[i * 4 + 0]; v.y = acc[i * 4 + 1];
        v.z = acc[i * 4 + 2]; v.w = acc[i * 4 + 3];
        ap[i * 32 + lane] = v;
    }
    if (lane == 0) {
        g_m[sidx] = m;
        g_l[sidx] = l;
    }
    __threadfence();                        // release partials
    if (lane == 0) atomicAdd(&g_cnt[b], 1);

    // ---- Phase 2: combine (64 designated CTAs, one batch each) ----
    if (blockIdx.x < COMBINE_CTA0) return;
    const int cb = blockIdx.x - COMBINE_CTA0;

    __shared__ float c_m[NSPLITS], c_l[NSPLITS], c_w[NSPLITS];

    if (tid == 0) {
        while (atomicAdd(&g_cnt[cb], 0) < NSPLITS) __nanosleep(100);
        __threadfence();                    // acquire partials
        g_cnt[cb] = 0;                      // reset for next graph replay
        g_cursor[cb] = 0;                   // reset work-steal cursor too
    }
    __syncthreads();

    if (tid < NSPLITS) {
        c_m[tid] = g_m[cb * NSPLITS + tid];
        c_l[tid] = g_l[cb * NSPLITS + tid];
    }
    __syncthreads();

    float mg = -CUDART_INF_F;
    #pragma unroll
    for (int i = 0; i < NSPLITS; i++) mg = fmaxf(mg, c_m[i]);
    if (tid < NSPLITS)
        c_w[tid] = (c_l[tid] > 0.0f) ? __expf(c_m[tid] - mg) : 0.0f;
    __syncthreads();

    float ltot = 0.0f;
    #pragma unroll
    for (int i = 0; i < NSPLITS; i++) ltot = fmaf(c_l[i], c_w[i], ltot);
    const float inv = 1.0f / ltot;

    float4 rr = make_float4(0.f, 0.f, 0.f, 0.f);
    const float4* accp = reinterpret_cast<const float4*>(g_acc) +
                         (size_t)cb * NSPLITS * (D_DIM / 4) + tid;
    #pragma unroll 8
    for (int i = 0; i < NSPLITS; i++) {
        const float4 a = accp[i * (D_DIM / 4)];
        const float wi = c_w[i];
        rr.x = fmaf(a.x, wi, rr.x);
        rr.y = fmaf(a.y, wi, rr.y);
        rr.z = fmaf(a.z, wi, rr.z);
        rr.w = fmaf(a.w, wi, rr.w);
    }
    rr.x *= inv; rr.y *= inv; rr.z *= inv; rr.w *= inv;
    reinterpret_cast<float4*>(out + (size_t)cb * D_DIM)[tid] = rr;
}

// ---------------------------------------------------------------------------
// Launch.  Inputs bound by element count:
//   B*S   = 131072    -> enc_mask (int32; JAX bool materialized as int32)
//   B*S*D = 134217728 -> enc_out  (f32)
//   B*D   = 65536     -> dec_hid  (f32)
// ---------------------------------------------------------------------------
extern "C" void kernel_launch(void* const* d_in, const int* in_sizes, int n_in,
                              void* d_out, int out_size)
{
    const int*   enc_mask = nullptr;
    const float* enc_out  = nullptr;
    const float* dec_hid  = nullptr;

    for (int i = 0; i < n_in; i++) {
        if (in_sizes[i] == B_DIM * S_DIM)            enc_mask = (const int*)d_in[i];
        else if (in_sizes[i] == B_DIM * D_DIM)       dec_hid  = (const float*)d_in[i];
        else                                          enc_out  = (const float*)d_in[i];
    }

    cudaFuncSetAttribute(luong_fused_kernel,
                         cudaFuncAttributeMaxDynamicSharedMemorySize,
                         DYN_SMEM_BYTES);

    luong_fused_kernel<<<GRID1, THREADS, DYN_SMEM_BYTES>>>(
        enc_mask, enc_out, dec_hid, (float*)d_out);
}

// round 10
// speedup vs baseline: 1.0821x; 1.0821x over previous
#include <cuda_runtime.h>
#include <cstdint>
#include <math_constants.h>

// Problem constants
#define B_DIM 64
#define S_DIM 2048
#define D_DIM 1024

// 296 CTAs x 8 warps = 2368 warps = 64 batches x 37 "slots".
// 296 = 148 SMs x occ 2 -> exactly one fully-resident wave (spin-safe).
#define WARPS_PER_CTA 8
#define THREADS (WARPS_PER_CTA * 32)
#define GRID1 296
#define NSPLITS 37
#define VEC 8                       // 8 float4 = 32 floats per lane
#define NSTAGES 3                   // cp.async ring depth per warp
#define CHUNK 8                     // rows per work-steal grab
#define NCHUNKS (S_DIM / CHUNK)     // 256 per batch
#define COMBINE_CTA0 (GRID1 - B_DIM)

#define RING_F4_PER_WARP (NSTAGES * (D_DIM / 4))
#define DYN_SMEM_BYTES (WARPS_PER_CTA * RING_F4_PER_WARP * 16)   // 96 KB

// Scratch (device globals: allocation-free)  ~9.7 MB
__device__ float g_acc[(size_t)B_DIM * NSPLITS * D_DIM];
__device__ float g_m[B_DIM * NSPLITS];
__device__ float g_l[B_DIM * NSPLITS];
__device__ int   g_cnt[B_DIM];      // arrivals; reset by combiner each run
__device__ int   g_cursor[B_DIM];   // steal cursors; reset by combiner

extern __shared__ float4 s_ring[];  // [WARPS_PER_CTA][NSTAGES][D_DIM/4]

__device__ __forceinline__ void waitg(int n) {
    if (n <= 0)      asm volatile("cp.async.wait_group 0;" ::: "memory");
    else if (n == 1) asm volatile("cp.async.wait_group 1;" ::: "memory");
    else             asm volatile("cp.async.wait_group 2;" ::: "memory");
}

// ---------------------------------------------------------------------------
// Fused kernel: dynamic work stealing with PREFETCHED grabs.
// The warp always holds a fully-resolved "next chunk" bitmap; the atomic
// cursor grab + mask load for the chunk after it are issued at switch time
// and their latency overlaps ~4 rows of streaming. The cp.async refill
// path therefore never waits on an atomic.
// ---------------------------------------------------------------------------
__global__ __launch_bounds__(THREADS, 2)
void luong_fused_kernel(const int*   __restrict__ enc_mask,
                        const float* __restrict__ enc_out,
                        const float* __restrict__ dec_hid,
                        float*       __restrict__ out)
{
    const int tid  = threadIdx.x;
    const int warp = tid >> 5;
    const int lane = tid & 31;
    const int gw   = blockIdx.x * WARPS_PER_CTA + warp;   // 0..2367
    const int b    = gw / NSPLITS;                        // batch
    const int s    = gw - b * NSPLITS;                    // partial slot

    float4* ring = s_ring + (size_t)warp * RING_F4_PER_WARP;

    // dec_hid slice in registers (8 float4 per lane)
    float4 h[VEC];
    {
        const float4* hp = reinterpret_cast<const float4*>(dec_hid + (size_t)b * D_DIM);
        #pragma unroll
        for (int i = 0; i < VEC; i++) h[i] = hp[i * 32 + lane];
    }

    const int*   mrow = enc_mask + (size_t)b * S_DIM;
    const float* base = enc_out + (size_t)b * S_DIM * D_DIM;

    // --- steal machinery: grab a chunk, resolve its unmasked-row bitmap ---
    auto fetch = [&](uint32_t& bits, int& cb) -> bool {
        int c = 0;
        if (lane == 0) c = atomicAdd(&g_cursor[b], 1);
        c = __shfl_sync(0xFFFFFFFFu, c, 0);
        if (c >= NCHUNKS) { bits = 0u; return false; }
        cb = c * CHUNK;
        const int mv = (lane < CHUNK) ? __ldg(mrow + cb + lane) : 1;
        bits = __ballot_sync(0xFFFFFFFFu, mv == 0);
        return true;
    };

    uint32_t cur_bits = 0u, nxt_bits = 0u;
    int      cur_base = 0,  nxt_base = 0;
    bool     have_nxt;

    // Prime: current chunk + one prefetched chunk
    have_nxt = fetch(cur_bits, cur_base);
    if (have_nxt) have_nxt = fetch(nxt_bits, nxt_base);

    auto next_row = [&]() -> int {          // next unmasked row or -1
        while (cur_bits == 0u) {
            if (!have_nxt) return -1;
            cur_bits = nxt_bits;            // instant switch (already resolved)
            cur_base = nxt_base;
            have_nxt = fetch(nxt_bits, nxt_base);   // latency hidden
        }
        const int r = cur_base + __ffs(cur_bits) - 1;
        cur_bits &= cur_bits - 1u;
        return r;
    };

    auto issue = [&](int st, int r) {       // async-load row r into stage st
        const float4* src = reinterpret_cast<const float4*>(base + (size_t)r * D_DIM);
        uint32_t dst0 = (uint32_t)__cvta_generic_to_shared(ring + st * (D_DIM / 4));
        #pragma unroll
        for (int i = 0; i < VEC; i++) {
            asm volatile("cp.async.cg.shared.global [%0], [%1], 16;"
                         :: "r"(dst0 + (uint32_t)((i * 32 + lane) * 16)),
                            "l"(src + i * 32 + lane) : "memory");
        }
        asm volatile("cp.async.commit_group;" ::: "memory");
    };

    float m = -CUDART_INF_F;
    float l = 0.0f;
    float acc[VEC * 4];
    #pragma unroll
    for (int j = 0; j < VEC * 4; j++) acc[j] = 0.0f;

    // Prologue: fill ring
    int r = next_row();
    int pend = 0, head = 0, tail = 0;
    while (r >= 0 && pend < NSTAGES) {
        issue(tail, r);
        tail = (tail + 1 == NSTAGES) ? 0 : tail + 1;
        pend++;
        r = next_row();
    }

    // Mainloop: consume oldest stage, refill it, advance
    while (pend > 0) {
        waitg(pend - 1);                    // oldest group complete
        pend--;

        const float4* xs = ring + head * (D_DIM / 4);

        float d0 = 0.f, d1 = 0.f, d2 = 0.f, d3 = 0.f;
        #pragma unroll
        for (int i = 0; i < VEC; i++) {
            const float4 v = xs[i * 32 + lane];
            d0 = fmaf(v.x, h[i].x, d0);
            d1 = fmaf(v.y, h[i].y, d1);
            d2 = fmaf(v.z, h[i].z, d2);
            d3 = fmaf(v.w, h[i].w, d3);
        }
        float dsum = (d0 + d1) + (d2 + d3);
        #pragma unroll
        for (int o = 16; o > 0; o >>= 1)
            dsum += __shfl_xor_sync(0xFFFFFFFFu, dsum, o);

        if (dsum > m) {                     // warp-uniform; ~log(n) times
            const float scale = __expf(m - dsum);   // exp(-inf)=0 first row
            l *= scale;
            #pragma unroll
            for (int j = 0; j < VEC * 4; j++) acc[j] *= scale;
            m = dsum;
        }
        const float p = __expf(dsum - m);
        l += p;
        #pragma unroll
        for (int i = 0; i < VEC; i++) {
            const float4 v = xs[i * 32 + lane];   // smem re-read (cheap)
            acc[i * 4 + 0] = fmaf(p, v.x, acc[i * 4 + 0]);
            acc[i * 4 + 1] = fmaf(p, v.y, acc[i * 4 + 1]);
            acc[i * 4 + 2] = fmaf(p, v.z, acc[i * 4 + 2]);
            acc[i * 4 + 3] = fmaf(p, v.w, acc[i * 4 + 3]);
        }

        if (r >= 0) {                       // refill freed stage
            issue(head, r);
            pend++;
            r = next_row();
        }
        head = (head + 1 == NSTAGES) ? 0 : head + 1;
    }

    // Publish partials, then release-arrive.
    const int sidx = b * NSPLITS + s;
    float4* ap = reinterpret_cast<float4*>(g_acc + (size_t)sidx * D_DIM);
    #pragma unroll
    for (int i = 0; i < VEC; i++) {
        float4 v;
        v.x = acc[i * 4 + 0]; v.y = acc[i * 4 + 1];
        v.z = acc[i * 4 + 2]; v.w = acc[i * 4 + 3];
        ap[i * 32 + lane] = v;
    }
    if (lane == 0) {
        g_m[sidx] = m;
        g_l[sidx] = l;
    }
    __threadfence();                        // release partials
    if (lane == 0) atomicAdd(&g_cnt[b], 1);

    // ---- Phase 2: combine (64 designated CTAs, one batch each) ----
    if (blockIdx.x < COMBINE_CTA0) return;
    const int cb = blockIdx.x - COMBINE_CTA0;

    __shared__ float c_m[NSPLITS], c_l[NSPLITS], c_w[NSPLITS];

    if (tid == 0) {
        while (atomicAdd(&g_cnt[cb], 0) < NSPLITS) __nanosleep(100);
        __threadfence();                    // acquire partials
        g_cnt[cb] = 0;                      // reset for next graph replay
        g_cursor[cb] = 0;                   // reset steal cursor too
    }
    __syncthreads();

    if (tid < NSPLITS) {
        c_m[tid] = g_m[cb * NSPLITS + tid];
        c_l[tid] = g_l[cb * NSPLITS + tid];
    }
    __syncthreads();

    float mg = -CUDART_INF_F;
    #pragma unroll
    for (int i = 0; i < NSPLITS; i++) mg = fmaxf(mg, c_m[i]);
    if (tid < NSPLITS)
        c_w[tid] = (c_l[tid] > 0.0f) ? __expf(c_m[tid] - mg) : 0.0f;
    __syncthreads();

    float ltot = 0.0f;
    #pragma unroll
    for (int i = 0; i < NSPLITS; i++) ltot = fmaf(c_l[i], c_w[i], ltot);
    const float inv = 1.0f / ltot;

    float4 rr = make_float4(0.f, 0.f, 0.f, 0.f);
    const float4* accp = reinterpret_cast<const float4*>(g_acc) +
                         (size_t)cb * NSPLITS * (D_DIM / 4) + tid;
    #pragma unroll 8
    for (int i = 0; i < NSPLITS; i++) {
        const float4 a = accp[i * (D_DIM / 4)];
        const float wi = c_w[i];
        rr.x = fmaf(a.x, wi, rr.x);
        rr.y = fmaf(a.y, wi, rr.y);
        rr.z = fmaf(a.z, wi, rr.z);
        rr.w = fmaf(a.w, wi, rr.w);
    }
    rr.x *= inv; rr.y *= inv; rr.z *= inv; rr.w *= inv;
    reinterpret_cast<float4*>(out + (size_t)cb * D_DIM)[tid] = rr;
}

// ---------------------------------------------------------------------------
// Launch.  Inputs bound by element count:
//   B*S   = 131072    -> enc_mask (int32; JAX bool materialized as int32)
//   B*S*D = 134217728 -> enc_out  (f32)
//   B*D   = 65536     -> dec_hid  (f32)
// ---------------------------------------------------------------------------
extern "C" void kernel_launch(void* const* d_in, const int* in_sizes, int n_in,
                              void* d_out, int out_size)
{
    const int*   enc_mask = nullptr;
    const float* enc_out  = nullptr;
    const float* dec_hid  = nullptr;

    for (int i = 0; i < n_in; i++) {
        if (in_sizes[i] == B_DIM * S_DIM)            enc_mask = (const int*)d_in[i];
        else if (in_sizes[i] == B_DIM * D_DIM)       dec_hid  = (const float*)d_in[i];
        else                                          enc_out  = (const float*)d_in[i];
    }

    cudaFuncSetAttribute(luong_fused_kernel,
                         cudaFuncAttributeMaxDynamicSharedMemorySize,
                         DYN_SMEM_BYTES);

    luong_fused_kernel<<<GRID1, THREADS, DYN_SMEM_BYTES>>>(
        enc_mask, enc_out, dec_hid, (float*)d_out);
}

// round 11
// speedup vs baseline: 1.1084x; 1.0243x over previous
#include <cuda_runtime.h>
#include <cstdint>
#include <math_constants.h>

// Problem constants
#define B_DIM 64
#define S_DIM 2048
#define D_DIM 1024

// 296 CTAs = 148 SMs x occ 2 -> one fully-resident wave (spin-safe).
// CTA i serves batch (i*64)/296  (4 or 5 CTAs per batch).
#define WARPS_PER_CTA 8
#define THREADS (WARPS_PER_CTA * 32)
#define GRID1 296
#define VEC 8                       // 8 float4 = 32 floats per lane
#define NSTAGES 3                   // cp.async ring depth per warp
#define CHUNK 8                     // rows per work-steal grab
#define NCHUNKS (S_DIM / CHUNK)     // 256 per batch
#define COMBINE_CTA0 (GRID1 - B_DIM)

#define RING_F4_PER_WARP (NSTAGES * (D_DIM / 4))
#define DYN_SMEM_BYTES (WARPS_PER_CTA * RING_F4_PER_WARP * 16)   // 96 KB

// Scratch (device globals: allocation-free)  ~1.2 MB
__device__ float g_acc[(size_t)GRID1 * D_DIM];   // one partial per CTA
__device__ float g_m[GRID1];
__device__ float g_l[GRID1];
__device__ int   g_cnt[B_DIM];      // CTA arrivals per batch; reset by combiner
__device__ int   g_cursor[B_DIM];   // steal cursors; reset by combiner

extern __shared__ float4 s_ring[];  // [WARPS_PER_CTA][NSTAGES][D_DIM/4]

__device__ __forceinline__ void waitg(int n) {
    if (n <= 0)      asm volatile("cp.async.wait_group 0;" ::: "memory");
    else if (n == 1) asm volatile("cp.async.wait_group 1;" ::: "memory");
    else             asm volatile("cp.async.wait_group 2;" ::: "memory");
}

// ---------------------------------------------------------------------------
// Fused kernel: per-warp streaming with prefetched work stealing, then an
// in-CTA smem merge (8 warp-partials -> 1 CTA-partial, ring reused as the
// merge buffer), then a tiny 4-5-way global combine per batch.
// ---------------------------------------------------------------------------
__global__ __launch_bounds__(THREADS, 2)
void luong_fused_kernel(const int*   __restrict__ enc_mask,
                        const float* __restrict__ enc_out,
                        const float* __restrict__ dec_hid,
                        float*       __restrict__ out)
{
    const int tid  = threadIdx.x;
    const int warp = tid >> 5;
    const int lane = tid & 31;
    const int b    = (blockIdx.x * B_DIM) / GRID1;        // CTA's batch

    float4* ring = s_ring + (size_t)warp * RING_F4_PER_WARP;

    __shared__ float s_m[WARPS_PER_CTA], s_l[WARPS_PER_CTA];

    // dec_hid slice in registers (8 float4 per lane)
    float4 h[VEC];
    {
        const float4* hp = reinterpret_cast<const float4*>(dec_hid + (size_t)b * D_DIM);
        #pragma unroll
        for (int i = 0; i < VEC; i++) h[i] = hp[i * 32 + lane];
    }

    const int*   mrow = enc_mask + (size_t)b * S_DIM;
    const float* base = enc_out + (size_t)b * S_DIM * D_DIM;

    // --- steal machinery: grab a chunk, resolve its unmasked-row bitmap ---
    auto fetch = [&](uint32_t& bits, int& cb) -> bool {
        int c = 0;
        if (lane == 0) c = atomicAdd(&g_cursor[b], 1);
        c = __shfl_sync(0xFFFFFFFFu, c, 0);
        if (c >= NCHUNKS) { bits = 0u; return false; }
        cb = c * CHUNK;
        const int mv = (lane < CHUNK) ? __ldg(mrow + cb + lane) : 1;
        bits = __ballot_sync(0xFFFFFFFFu, mv == 0);
        return true;
    };

    uint32_t cur_bits = 0u, nxt_bits = 0u;
    int      cur_base = 0,  nxt_base = 0;
    bool     have_nxt;

    have_nxt = fetch(cur_bits, cur_base);
    if (have_nxt) have_nxt = fetch(nxt_bits, nxt_base);

    auto next_row = [&]() -> int {          // next unmasked row or -1
        while (cur_bits == 0u) {
            if (!have_nxt) return -1;
            cur_bits = nxt_bits;            // instant switch (already resolved)
            cur_base = nxt_base;
            have_nxt = fetch(nxt_bits, nxt_base);   // latency hidden
        }
        const int r = cur_base + __ffs(cur_bits) - 1;
        cur_bits &= cur_bits - 1u;
        return r;
    };

    auto issue = [&](int st, int r) {       // async-load row r into stage st
        const float4* src = reinterpret_cast<const float4*>(base + (size_t)r * D_DIM);
        uint32_t dst0 = (uint32_t)__cvta_generic_to_shared(ring + st * (D_DIM / 4));
        #pragma unroll
        for (int i = 0; i < VEC; i++) {
            asm volatile("cp.async.cg.shared.global [%0], [%1], 16;"
                         :: "r"(dst0 + (uint32_t)((i * 32 + lane) * 16)),
                            "l"(src + i * 32 + lane) : "memory");
        }
        asm volatile("cp.async.commit_group;" ::: "memory");
    };

    float m = -CUDART_INF_F;
    float l = 0.0f;
    float acc[VEC * 4];
    #pragma unroll
    for (int j = 0; j < VEC * 4; j++) acc[j] = 0.0f;

    // Prologue: fill ring
    int r = next_row();
    int pend = 0, head = 0, tail = 0;
    while (r >= 0 && pend < NSTAGES) {
        issue(tail, r);
        tail = (tail + 1 == NSTAGES) ? 0 : tail + 1;
        pend++;
        r = next_row();
    }

    // Mainloop: consume oldest stage, refill it, advance
    while (pend > 0) {
        waitg(pend - 1);
        pend--;

        const float4* xs = ring + head * (D_DIM / 4);

        float d0 = 0.f, d1 = 0.f, d2 = 0.f, d3 = 0.f;
        #pragma unroll
        for (int i = 0; i < VEC; i++) {
            const float4 v = xs[i * 32 + lane];
            d0 = fmaf(v.x, h[i].x, d0);
            d1 = fmaf(v.y, h[i].y, d1);
            d2 = fmaf(v.z, h[i].z, d2);
            d3 = fmaf(v.w, h[i].w, d3);
        }
        float dsum = (d0 + d1) + (d2 + d3);
        #pragma unroll
        for (int o = 16; o > 0; o >>= 1)
            dsum += __shfl_xor_sync(0xFFFFFFFFu, dsum, o);

        if (dsum > m) {                     // warp-uniform; ~log(n) times
            const float scale = __expf(m - dsum);   // exp(-inf)=0 first row
            l *= scale;
            #pragma unroll
            for (int j = 0; j < VEC * 4; j++) acc[j] *= scale;
            m = dsum;
        }
        const float p = __expf(dsum - m);
        l += p;
        #pragma unroll
        for (int i = 0; i < VEC; i++) {
            const float4 v = xs[i * 32 + lane];   // smem re-read (cheap)
            acc[i * 4 + 0] = fmaf(p, v.x, acc[i * 4 + 0]);
            acc[i * 4 + 1] = fmaf(p, v.y, acc[i * 4 + 1]);
            acc[i * 4 + 2] = fmaf(p, v.z, acc[i * 4 + 2]);
            acc[i * 4 + 3] = fmaf(p, v.w, acc[i * 4 + 3]);
        }

        if (r >= 0) {
            issue(head, r);
            pend++;
            r = next_row();
        }
        head = (head + 1 == NSTAGES) ? 0 : head + 1;
    }

    // ---- In-CTA merge: 8 warp-partials -> 1 CTA partial (ring reused) ----
    if (lane == 0) { s_m[warp] = m; s_l[warp] = l; }
    __syncthreads();

    float m_cta = -CUDART_INF_F;
    #pragma unroll
    for (int i = 0; i < WARPS_PER_CTA; i++) m_cta = fmaxf(m_cta, s_m[i]);
    float l_cta = 0.0f;
    #pragma unroll
    for (int i = 0; i < WARPS_PER_CTA; i++) {
        const float wi = (s_l[i] > 0.0f) ? __expf(s_m[i] - m_cta) : 0.0f;
        l_cta = fmaf(s_l[i], wi, l_cta);
    }
    const float w_me = (l > 0.0f) ? __expf(m - m_cta) : 0.0f;

    // Park scaled acc in own ring region (f4 index fi = i*32+lane -> cols fi*4..)
    #pragma unroll
    for (int i = 0; i < VEC; i++) {
        float4 v;
        v.x = acc[i * 4 + 0] * w_me; v.y = acc[i * 4 + 1] * w_me;
        v.z = acc[i * 4 + 2] * w_me; v.w = acc[i * 4 + 3] * w_me;
        ring[i * 32 + lane] = v;
    }
    __syncthreads();

    // Warp `warp` sums column-slice fi = warp*32 + lane across all 8 slots
    {
        const int fi = warp * 32 + lane;
        float4 sum = s_ring[fi];
        #pragma unroll
        for (int w = 1; w < WARPS_PER_CTA; w++) {
            const float4 a = s_ring[(size_t)w * RING_F4_PER_WARP + fi];
            sum.x += a.x; sum.y += a.y; sum.z += a.z; sum.w += a.w;
        }
        reinterpret_cast<float4*>(g_acc + (size_t)blockIdx.x * D_DIM)[fi] = sum;
    }
    if (tid == 0) {
        g_m[blockIdx.x] = m_cta;
        g_l[blockIdx.x] = l_cta;
    }
    __threadfence();                        // release partial
    __syncthreads();
    if (tid == 0) atomicAdd(&g_cnt[b], 1);

    // ---- Combine: last 64 CTAs, one batch each (4-5 partials) ----
    if (blockIdx.x < COMBINE_CTA0) return;
    const int cb = blockIdx.x - COMBINE_CTA0;

    const int j0 = (cb * GRID1 + B_DIM - 1) / B_DIM;        // first CTA of batch
    const int j1 = ((cb + 1) * GRID1 + B_DIM - 1) / B_DIM;  // one past last
    const int nparts = j1 - j0;                             // 4 or 5

    if (tid == 0) {
        while (atomicAdd(&g_cnt[cb], 0) < nparts) __nanosleep(100);
        __threadfence();                    // acquire partials
        g_cnt[cb] = 0;                      // reset for next graph replay
        g_cursor[cb] = 0;
    }
    __syncthreads();

    float mg = -CUDART_INF_F;
    for (int j = j0; j < j1; j++) mg = fmaxf(mg, g_m[j]);

    float ws[5];
    float ltot = 0.0f;
    for (int jj = 0; jj < nparts; jj++) {
        const float lj = g_l[j0 + jj];
        const float wj = (lj > 0.0f) ? __expf(g_m[j0 + jj] - mg) : 0.0f;
        ws[jj] = wj;
        ltot = fmaf(lj, wj, ltot);
    }
    const float inv = 1.0f / ltot;

    float4 rr = make_float4(0.f, 0.f, 0.f, 0.f);
    #pragma unroll 5
    for (int jj = 0; jj < nparts; jj++) {
        const float4 a = reinterpret_cast<const float4*>(
            g_acc + (size_t)(j0 + jj) * D_DIM)[tid];
        const float wj = ws[jj];
        rr.x = fmaf(a.x, wj, rr.x);
        rr.y = fmaf(a.y, wj, rr.y);
        rr.z = fmaf(a.z, wj, rr.z);
        rr.w = fmaf(a.w, wj, rr.w);
    }
    rr.x *= inv; rr.y *= inv; rr.z *= inv; rr.w *= inv;
    reinterpret_cast<float4*>(out + (size_t)cb * D_DIM)[tid] = rr;
}

// ---------------------------------------------------------------------------
// Launch.  Inputs bound by element count:
//   B*S   = 131072    -> enc_mask (int32; JAX bool materialized as int32)
//   B*S*D = 134217728 -> enc_out  (f32)
//   B*D   = 65536     -> dec_hid  (f32)
// ---------------------------------------------------------------------------
extern "C" void kernel_launch(void* const* d_in, const int* in_sizes, int n_in,
                              void* d_out, int out_size)
{
    const int*   enc_mask = nullptr;
    const float* enc_out  = nullptr;
    const float* dec_hid  = nullptr;

    for (int i = 0; i < n_in; i++) {
        if (in_sizes[i] == B_DIM * S_DIM)            enc_mask = (const int*)d_in[i];
        else if (in_sizes[i] == B_DIM * D_DIM)       dec_hid  = (const float*)d_in[i];
        else                                          enc_out  = (const float*)d_in[i];
    }

    cudaFuncSetAttribute(luong_fused_kernel,
                         cudaFuncAttributeMaxDynamicSharedMemorySize,
                         DYN_SMEM_BYTES);

    luong_fused_kernel<<<GRID1, THREADS, DYN_SMEM_BYTES>>>(
        enc_mask, enc_out, dec_hid, (float*)d_out);
}

// round 14
// speedup vs baseline: 1.1130x; 1.0042x over previous
#include <cuda_runtime.h>
#include <cstdint>
#include <math_constants.h>

// Problem constants
#define B_DIM 64
#define S_DIM 2048
#define D_DIM 1024

// 296 CTAs = 148 SMs x occ 2 -> one fully-resident wave (spin-safe).
// CTA i serves batch (i*64)/296  (4 or 5 CTAs per batch).
#define WARPS_PER_CTA 8
#define THREADS (WARPS_PER_CTA * 32)
#define GRID1 296
#define VEC 8                       // 8 float4 = 32 floats per lane
#define NSTAGES 3                   // TMA ring depth per warp
#define CHUNK 8                     // rows per work-steal grab
#define NCHUNKS (S_DIM / CHUNK)     // 256 per batch
#define COMBINE_CTA0 (GRID1 - B_DIM)
#define ROW_BYTES (D_DIM * 4)       // 4096

#define RING_F4_PER_WARP (NSTAGES * (D_DIM / 4))
#define DYN_SMEM_BYTES (WARPS_PER_CTA * RING_F4_PER_WARP * 16)   // 96 KB

// Scratch (device globals: allocation-free)  ~1.2 MB
__device__ float g_acc[(size_t)GRID1 * D_DIM];   // one partial per CTA
__device__ float g_m[GRID1];
__device__ float g_l[GRID1];
__device__ int   g_cnt[B_DIM];      // CTA arrivals per batch; reset by combiner
__device__ int   g_cursor[B_DIM];   // steal cursors; reset by combiner

extern __shared__ float4 s_ring[];  // [WARPS_PER_CTA][NSTAGES][D_DIM/4]

__device__ __forceinline__ void mbar_wait(uint32_t mbar, uint32_t parity) {
    asm volatile(
        "{\n\t"
        ".reg .pred P;\n\t"
        "W_%=:\n\t"
        "mbarrier.try_wait.parity.acquire.cta.shared::cta.b64 P, [%0], %1, 0x989680;\n\t"
        "@P bra D_%=;\n\t"
        "bra W_%=;\n\t"
        "D_%=:\n\t"
        "}"
        :: "r"(mbar), "r"(parity) : "memory");
}

// ---------------------------------------------------------------------------
// Fused kernel: per-warp streaming via 1D TMA bulk copies (one 4 KB
// cp.async.bulk per row, mbarrier complete_tx), prefetched work stealing,
// in-CTA smem merge (8 warp-partials -> 1 CTA-partial), tiny global combine.
// ---------------------------------------------------------------------------
__global__ __launch_bounds__(THREADS, 2)
void luong_fused_kernel(const int*   __restrict__ enc_mask,
                        const float* __restrict__ enc_out,
                        const float* __restrict__ dec_hid,
                        float*       __restrict__ out)
{
    const int tid  = threadIdx.x;
    const int warp = tid >> 5;
    const int lane = tid & 31;
    const int b    = (blockIdx.x * B_DIM) / GRID1;        // CTA's batch

    float4* ring = s_ring + (size_t)warp * RING_F4_PER_WARP;

    __shared__ __align__(8) uint64_t s_mbar[WARPS_PER_CTA][NSTAGES];
    __shared__ float s_m[WARPS_PER_CTA], s_l[WARPS_PER_CTA];

    // Init this warp's stage mbarriers (count=1: the producer's expect_tx arrive)
    if (lane == 0) {
        #pragma unroll
        for (int st = 0; st < NSTAGES; st++) {
            uint32_t mb = (uint32_t)__cvta_generic_to_shared(&s_mbar[warp][st]);
            asm volatile("mbarrier.init.shared.b64 [%0], 1;" :: "r"(mb) : "memory");
        }
    }
    __syncwarp();

    // dec_hid slice in registers (8 float4 per lane)
    float4 h[VEC];
    {
        const float4* hp = reinterpret_cast<const float4*>(dec_hid + (size_t)b * D_DIM);
        #pragma unroll
        for (int i = 0; i < VEC; i++) h[i] = hp[i * 32 + lane];
    }

    const int*   mrow = enc_mask + (size_t)b * S_DIM;
    const float* base = enc_out + (size_t)b * S_DIM * D_DIM;

    // --- steal machinery: grab a chunk, resolve its unmasked-row bitmap ---
    auto fetch = [&](uint32_t& bits, int& cb) -> bool {
        int c = 0;
        if (lane == 0) c = atomicAdd(&g_cursor[b], 1);
        c = __shfl_sync(0xFFFFFFFFu, c, 0);
        if (c >= NCHUNKS) { bits = 0u; return false; }
        cb = c * CHUNK;
        const int mv = (lane < CHUNK) ? __ldg(mrow + cb + lane) : 1;
        bits = __ballot_sync(0xFFFFFFFFu, mv == 0);
        return true;
    };

    uint32_t cur_bits = 0u, nxt_bits = 0u;
    int      cur_base = 0,  nxt_base = 0;
    bool     have_nxt;

    have_nxt = fetch(cur_bits, cur_base);
    if (have_nxt) have_nxt = fetch(nxt_bits, nxt_base);

    auto next_row = [&]() -> int {          // next unmasked row or -1
        while (cur_bits == 0u) {
            if (!have_nxt) return -1;
            cur_bits = nxt_bits;            // instant switch (already resolved)
            cur_base = nxt_base;
            have_nxt = fetch(nxt_bits, nxt_base);   // latency hidden
        }
        const int r = cur_base + __ffs(cur_bits) - 1;
        cur_bits &= cur_bits - 1u;
        return r;
    };

    // One 4 KB TMA bulk copy per row (lane 0 only): expect_tx then bulk.
    auto issue = [&](int st, int r) {
        if (lane == 0) {
            uint32_t mb  = (uint32_t)__cvta_generic_to_shared(&s_mbar[warp][st]);
            uint32_t dst = (uint32_t)__cvta_generic_to_shared(ring + st * (D_DIM / 4));
            const float* src = base + (size_t)r * D_DIM;
            asm volatile("mbarrier.arrive.expect_tx.shared.b64 _, [%0], %1;"
                         :: "r"(mb), "r"((uint32_t)ROW_BYTES) : "memory");
            asm volatile("cp.async.bulk.shared::cta.global.mbarrier::complete_tx::bytes "
                         "[%0], [%1], %2, [%3];"
                         :: "r"(dst), "l"(src), "r"((uint32_t)ROW_BYTES), "r"(mb)
                         : "memory");
        }
    };

    unsigned ph = 0;                        // per-stage phase-parity bits

    float m = -CUDART_INF_F;
    float l = 0.0f;
    float acc[VEC * 4];
    #pragma unroll
    for (int j = 0; j < VEC * 4; j++) acc[j] = 0.0f;

    // Prologue: fill ring
    int r = next_row();
    int pend = 0, head = 0, tail = 0;
    while (r >= 0 && pend < NSTAGES) {
        issue(tail, r);
        tail = (tail + 1 == NSTAGES) ? 0 : tail + 1;
        pend++;
        r = next_row();
    }

    // Mainloop: wait oldest stage, consume, refill, advance
    while (pend > 0) {
        {
            uint32_t mb = (uint32_t)__cvta_generic_to_shared(&s_mbar[warp][head]);
            mbar_wait(mb, (ph >> head) & 1u);
            ph ^= 1u << head;               // next use of this slot: flipped parity
        }
        pend--;

        const float4* xs = ring + head * (D_DIM / 4);

        float d0 = 0.f, d1 = 0.f, d2 = 0.f, d3 = 0.f;
        #pragma unroll
        for (int i = 0; i < VEC; i++) {
            const float4 v = xs[i * 32 + lane];
            d0 = fmaf(v.x, h[i].x, d0);
            d1 = fmaf(v.y, h[i].y, d1);
            d2 = fmaf(v.z, h[i].z, d2);
            d3 = fmaf(v.w, h[i].w, d3);
        }
        float dsum = (d0 + d1) + (d2 + d3);
        #pragma unroll
        for (int o = 16; o > 0; o >>= 1)
            dsum += __shfl_xor_sync(0xFFFFFFFFu, dsum, o);

        if (dsum > m) {                     // warp-uniform; ~log(n) times
            const float scale = __expf(m - dsum);   // exp(-inf)=0 first row
            l *= scale;
            #pragma unroll
            for (int j = 0; j < VEC * 4; j++) acc[j] *= scale;
            m = dsum;
        }
        const float p = __expf(dsum - m);
        l += p;
        #pragma unroll
        for (int i = 0; i < VEC; i++) {
            const float4 v = xs[i * 32 + lane];   // smem re-read
            acc[i * 4 + 0] = fmaf(p, v.x, acc[i * 4 + 0]);
            acc[i * 4 + 1] = fmaf(p, v.y, acc[i * 4 + 1]);
            acc[i * 4 + 2] = fmaf(p, v.z, acc[i * 4 + 2]);
            acc[i * 4 + 3] = fmaf(p, v.w, acc[i * 4 + 3]);
        }

        if (r >= 0) {                       // refill freed stage
            issue(head, r);
            pend++;
            r = next_row();
        }
        head = (head + 1 == NSTAGES) ? 0 : head + 1;
    }

    // ---- In-CTA merge: 8 warp-partials -> 1 CTA partial (ring reused) ----
    if (lane == 0) { s_m[warp] = m; s_l[warp] = l; }
    __syncthreads();

    float m_cta = -CUDART_INF_F;
    #pragma unroll
    for (int i = 0; i < WARPS_PER_CTA; i++) m_cta = fmaxf(m_cta, s_m[i]);
    float l_cta = 0.0f;
    #pragma unroll
    for (int i = 0; i < WARPS_PER_CTA; i++) {
        const float wi = (s_l[i] > 0.0f) ? __expf(s_m[i] - m_cta) : 0.0f;
        l_cta = fmaf(s_l[i], wi, l_cta);
    }
    const float w_me = (l > 0.0f) ? __expf(m - m_cta) : 0.0f;

    // Park scaled acc in own ring region
    #pragma unroll
    for (int i = 0; i < VEC; i++) {
        float4 v;
        v.x = acc[i * 4 + 0] * w_me; v.y = acc[i * 4 + 1] * w_me;
        v.z = acc[i * 4 + 2] * w_me; v.w = acc[i * 4 + 3] * w_me;
        ring[i * 32 + lane] = v;
    }
    __syncthreads();

    // Warp `warp` sums column-slice fi = warp*32 + lane across all 8 slots
    {
        const int fi = warp * 32 + lane;
        float4 sum = s_ring[fi];
        #pragma unroll
        for (int w = 1; w < WARPS_PER_CTA; w++) {
            const float4 a = s_ring[(size_t)w * RING_F4_PER_WARP + fi];
            sum.x += a.x; sum.y += a.y; sum.z += a.z; sum.w += a.w;
        }
        reinterpret_cast<float4*>(g_acc + (size_t)blockIdx.x * D_DIM)[fi] = sum;
    }
    if (tid == 0) {
        g_m[blockIdx.x] = m_cta;
        g_l[blockIdx.x] = l_cta;
    }
    __threadfence();                        // release partial
    __syncthreads();
    if (tid == 0) atomicAdd(&g_cnt[b], 1);

    // ---- Combine: last 64 CTAs, one batch each (4-5 partials) ----
    if (blockIdx.x < COMBINE_CTA0) return;
    const int cb = blockIdx.x - COMBINE_CTA0;

    const int j0 = (cb * GRID1 + B_DIM - 1) / B_DIM;        // first CTA of batch
    const int j1 = ((cb + 1) * GRID1 + B_DIM - 1) / B_DIM;  // one past last
    const int nparts = j1 - j0;                             // 4 or 5

    if (tid == 0) {
        while (atomicAdd(&g_cnt[cb], 0) < nparts) __nanosleep(100);
        __threadfence();                    // acquire partials
        g_cnt[cb] = 0;                      // reset for next graph replay
        g_cursor[cb] = 0;
    }
    __syncthreads();

    float mg = -CUDART_INF_F;
    for (int j = j0; j < j1; j++) mg = fmaxf(mg, g_m[j]);

    float ws[5];
    float ltot = 0.0f;
    for (int jj = 0; jj < nparts; jj++) {
        const float lj = g_l[j0 + jj];
        const float wj = (lj > 0.0f) ? __expf(g_m[j0 + jj] - mg) : 0.0f;
        ws[jj] = wj;
        ltot = fmaf(lj, wj, ltot);
    }
    const float inv = 1.0f / ltot;

    float4 rr = make_float4(0.f, 0.f, 0.f, 0.f);
    #pragma unroll 5
    for (int jj = 0; jj < nparts; jj++) {
        const float4 a = reinterpret_cast<const float4*>(
            g_acc + (size_t)(j0 + jj) * D_DIM)[tid];
        const float wj = ws[jj];
        rr.x = fmaf(a.x, wj, rr.x);
        rr.y = fmaf(a.y, wj, rr.y);
        rr.z = fmaf(a.z, wj, rr.z);
        rr.w = fmaf(a.w, wj, rr.w);
    }
    rr.x *= inv; rr.y *= inv; rr.z *= inv; rr.w *= inv;
    reinterpret_cast<float4*>(out + (size_t)cb * D_DIM)[tid] = rr;
}

// ---------------------------------------------------------------------------
// Launch.  Inputs bound by element count:
//   B*S   = 131072    -> enc_mask (int32; JAX bool materialized as int32)
//   B*S*D = 134217728 -> enc_out  (f32)
//   B*D   = 65536     -> dec_hid  (f32)
// ---------------------------------------------------------------------------
extern "C" void kernel_launch(void* const* d_in, const int* in_sizes, int n_in,
                              void* d_out, int out_size)
{
    const int*   enc_mask = nullptr;
    const float* enc_out  = nullptr;
    const float* dec_hid  = nullptr;

    for (int i = 0; i < n_in; i++) {
        if (in_sizes[i] == B_DIM * S_DIM)            enc_mask = (const int*)d_in[i];
        else if (in_sizes[i] == B_DIM * D_DIM)       dec_hid  = (const float*)d_in[i];
        else                                          enc_out  = (const float*)d_in[i];
    }

    cudaFuncSetAttribute(luong_fused_kernel,
                         cudaFuncAttributeMaxDynamicSharedMemorySize,
                         DYN_SMEM_BYTES);

    luong_fused_kernel<<<GRID1, THREADS, DYN_SMEM_BYTES>>>(
        enc_mask, enc_out, dec_hid, (float*)d_out);
}